// round 1
// baseline (speedup 1.0000x reference)
#include <cuda_runtime.h>

// ----------------------------------------------------------------------------
// Hopf oscillator CPG step, reformulated:
//   sin(psi_j - psi_i - phi_ij) = (s_j c_i - c_j s_i)cos(phi) - (c_j c_i + s_j s_i)sin(phi)
// With A_ij = w_zd*cos(phi_zd), B_ij = w_zd*sin(phi_zd), x_j = r_j s_j, y_j = r_j c_j:
//   coupling_i = c_i*(A x - B y)_i - s_i*(A y + B x)_i
// => per batch row: 32 sincos + 4 real 32x32 matvecs (done as packed f32x2 FMAs,
//    pairing two batch rows per FFMA2 lane).
// ----------------------------------------------------------------------------

#define PI2F 6.28318530717958647692f

typedef unsigned long long u64;

// Precomputed per-launch constants (prep kernel writes, main kernel reads).
__device__ float2 gAA[1024];   // {A_ij, A_ij}
__device__ float2 gBB[1024];   // {B_ij, B_ij}
__device__ float  gTPV[32];    // 2*pi*V_MAX*sigmoid(v)
__device__ float  gBA[32];     // B_MAX*sigmoid(b)
__device__ float  gCA[32];     // C_MAX*sigmoid(c)

__global__ void prep_kernel(const float* __restrict__ v, const float* __restrict__ b,
                            const float* __restrict__ c, const float* __restrict__ w,
                            const float* __restrict__ phi) {
    int m = threadIdx.x;  // 0..1023, m = i*32 + j
    float A = 0.0f, Bv = 0.0f;
    // zero-diag mapping: flat index m is diagonal iff m % 33 == 0
    if (m % 33 != 0) {
        int k  = m / 33;        // 0..30
        int jj = m % 33 - 1;    // 0..31
        float wv = w[k * 32 + jj];
        float pv = phi[k * 32 + jj];
        float wa = 1.0f / (1.0f + expf(-wv));      // W_MAX = 1
        float pa = PI2F / (1.0f + expf(-pv));      // PHI_MAX = 2*pi
        float sp, cp;
        sincosf(pa, &sp, &cp);
        A  = wa * cp;
        Bv = wa * sp;
    }
    gAA[m] = make_float2(A, A);
    gBB[m] = make_float2(Bv, Bv);
    if (m < 32) {
        gTPV[m] = (PI2F * 5.0f) / (1.0f + expf(-v[m]));
        gBA[m]  = 2.0f  / (1.0f + expf(-b[m]));
        gCA[m]  = 10.0f / (1.0f + expf(-c[m]));
    }
}

__device__ __forceinline__ u64 pack2(float lo, float hi) {
    u64 r;
    asm("mov.b64 %0, {%1, %2};" : "=l"(r) : "f"(lo), "f"(hi));
    return r;
}
__device__ __forceinline__ void unpack2(u64 v, float& lo, float& hi) {
    asm("mov.b64 {%0, %1}, %2;" : "=f"(lo), "=f"(hi) : "l"(v));
}
// Packed dual fp32 FMA (Blackwell f32x2 pipe) — acc.{lo,hi} += a.{lo,hi}*b.{lo,hi}
#define FMA2(acc, a, b) asm("fma.rn.f32x2 %0, %1, %2, %0;" : "+l"(acc) : "l"(a), "l"(b))

__global__ __launch_bounds__(256)
void hopf_kernel(const float* __restrict__ in, float* __restrict__ out, int nrows) {
    const int lane = threadIdx.x & 31;      // oscillator index i
    const int wib  = threadIdx.x >> 5;      // warp in block (0..7)
    const int gw   = blockIdx.x * 8 + wib;  // global warp id

    __shared__ float4 sXY[8][2][32];        // per-warp {x0,x1,y0,y1} broadcast buffers

    // per-lane constants
    const float tpv = gTPV[lane];
    const float ba  = gBA[lane];
    const float ca  = gCA[lane];

    // matrix row i in registers, pre-packed {A,A} / {B,B}
    u64 AA[32], BB[32];
    {
        const u64* pA = reinterpret_cast<const u64*>(gAA) + lane * 32;
        const u64* pB = reinterpret_cast<const u64*>(gBB) + lane * 32;
        #pragma unroll
        for (int j = 0; j < 32; j++) { AA[j] = pA[j]; BB[j] = pB[j]; }
    }

    const int rowBase = gw * 8;   // 8 rows per warp (two 4-row quads)

    #pragma unroll
    for (int q = 0; q < 2; q++) {
        const int r0 = rowBase + q * 4;
        float sv[4], cv[4], xv[4], yv[4];

        #pragma unroll
        for (int t = 0; t < 4; t++) {
            const int row = r0 + t;
            float psi = 0.0f, rr = 0.0f, rd = 0.0f;
            if (row < nrows) {
                const float* rp = in + (size_t)row * 96;
                psi = rp[lane];
                rr  = rp[32 + lane];
                rd  = rp[64 + lane];
            }
            __sincosf(psi, &sv[t], &cv[t]);
            xv[t] = rr * sv[t];
            yv[t] = rr * cv[t];
            if (row < nrows) {
                // r_d and r_d_dot outputs don't need the coupling — store now.
                float rdd = ca * (0.25f * ca * (ba - rr) - rd);
                float* op = out + (size_t)row * 96;
                op[32 + lane] = rd;
                op[64 + lane] = rdd;
            }
        }

        __syncwarp();  // previous quad's readers done before overwrite
        sXY[wib][0][lane] = make_float4(xv[0], xv[1], yv[0], yv[1]);
        sXY[wib][1][lane] = make_float4(xv[2], xv[3], yv[2], yv[3]);
        __syncwarp();

        // Four accumulators per row-pair: P1=sum(Ax), P2=sum(By), Q1=sum(Ay), Q2=sum(Bx)
        u64 aP1 = 0, aP2 = 0, aQ1 = 0, aQ2 = 0;   // rows (0,1)
        u64 bP1 = 0, bP2 = 0, bQ1 = 0, bQ2 = 0;   // rows (2,3)

        #pragma unroll
        for (int j = 0; j < 32; j++) {
            float4 v0 = sXY[wib][0][j];   // broadcast LDS.128
            float4 v1 = sXY[wib][1][j];
            u64 X0 = pack2(v0.x, v0.y), Y0 = pack2(v0.z, v0.w);
            u64 X1 = pack2(v1.x, v1.y), Y1 = pack2(v1.z, v1.w);
            FMA2(aP1, AA[j], X0);  FMA2(aP2, BB[j], Y0);
            FMA2(aQ1, AA[j], Y0);  FMA2(aQ2, BB[j], X0);
            FMA2(bP1, AA[j], X1);  FMA2(bP2, BB[j], Y1);
            FMA2(bQ1, AA[j], Y1);  FMA2(bQ2, BB[j], X1);
        }

        float P[4], Q[4];
        {
            float l0,h0,l1,h1,l2,h2,l3,h3;
            unpack2(aP1,l0,h0); unpack2(aP2,l1,h1);
            unpack2(aQ1,l2,h2); unpack2(aQ2,l3,h3);
            P[0] = l0 - l1;  P[1] = h0 - h1;
            Q[0] = l2 + l3;  Q[1] = h2 + h3;
        }
        {
            float l0,h0,l1,h1,l2,h2,l3,h3;
            unpack2(bP1,l0,h0); unpack2(bP2,l1,h1);
            unpack2(bQ1,l2,h2); unpack2(bQ2,l3,h3);
            P[2] = l0 - l1;  P[3] = h0 - h1;
            Q[2] = l2 + l3;  Q[3] = h2 + h3;
        }

        #pragma unroll
        for (int t = 0; t < 4; t++) {
            const int row = r0 + t;
            if (row < nrows) {
                float psi_dot = tpv + cv[t] * P[t] - sv[t] * Q[t];
                out[(size_t)row * 96 + lane] = psi_dot;
            }
        }
    }
}

extern "C" void kernel_launch(void* const* d_in, const int* in_sizes, int n_in,
                              void* d_out, int out_size) {
    const float* states = (const float*)d_in[0];
    const float* v      = (const float*)d_in[1];
    const float* b      = (const float*)d_in[2];
    const float* c      = (const float*)d_in[3];
    const float* w      = (const float*)d_in[4];
    const float* phi    = (const float*)d_in[5];
    float* out = (float*)d_out;

    const int nrows = in_sizes[0] / 96;   // 65536
    prep_kernel<<<1, 1024>>>(v, b, c, w, phi);

    const int rows_per_warp = 8;
    const int warps  = (nrows + rows_per_warp - 1) / rows_per_warp;
    const int blocks = (warps + 7) / 8;   // 8 warps (256 threads) per block
    hopf_kernel<<<blocks, 256>>>(states, out, nrows);
}

// round 2
// speedup vs baseline: 3.2087x; 3.2087x over previous
#include <cuda_runtime.h>

// Hopf oscillator CPG step, reformulated:
//   sin(psi_j - psi_i - phi_ij) = (s_j c_i - c_j s_i)cos(phi) - (c_j c_i + s_j s_i)sin(phi)
// A_ij = w_zd*cos(phi_zd), B_ij = w_zd*sin(phi_zd), x_j = r_j s_j, y_j = r_j c_j:
//   coupling_i = c_i*(A x - B y)_i - s_i*(A y + B x)_i
// Matrix lives in SHARED memory [j][i] (conflict-free), computed per-block from the
// raw params (cheap: ~24 MUFU/thread once). Packed f32x2 FMAs pair two batch rows.

#define PI2F 6.28318530717958647692f

typedef unsigned long long u64;

__device__ __forceinline__ u64 pack2(float lo, float hi) {
    u64 r;
    asm("mov.b64 %0, {%1, %2};" : "=l"(r) : "f"(lo), "f"(hi));
    return r;
}
__device__ __forceinline__ void unpack2(u64 v, float& lo, float& hi) {
    asm("mov.b64 {%0, %1}, %2;" : "=f"(lo), "=f"(hi) : "l"(v));
}
#define FMA2(acc, a, b) asm("fma.rn.f32x2 %0, %1, %2, %0;" : "+l"(acc) : "l"(a), "l"(b))

__device__ __forceinline__ float fsigmoid(float x) {
    return 1.0f / (1.0f + __expf(-x));
}

__global__ __launch_bounds__(256, 4)
void hopf_kernel(const float* __restrict__ in, float* __restrict__ out,
                 const float* __restrict__ v, const float* __restrict__ b,
                 const float* __restrict__ c, const float* __restrict__ w,
                 const float* __restrict__ phi, int nrows) {
    const int tid  = threadIdx.x;
    const int lane = tid & 31;          // oscillator index i
    const int wib  = tid >> 5;          // warp in block (0..7)
    const int gw   = blockIdx.x * 8 + wib;

    // sAB[j*32 + i] = {A[i][j], B[i][j]}  -> lane-consecutive LDS.64, conflict-free
    __shared__ float2 sAB[1024];
    __shared__ float4 sXY[8][2][32];    // per-warp {x0,x1,y0,y1} broadcast buffers

    // ---- build activation matrix directly in smem (4 entries per thread) ----
    #pragma unroll
    for (int k = 0; k < 4; k++) {
        int m = tid + k * 256;          // flat index, i = m/32, j = m%32
        float A = 0.0f, Bv = 0.0f;
        if (m % 33 != 0) {              // zero-diag: diagonal iff m % 33 == 0
            int kk = m / 33;            // 0..30
            int jj = m % 33 - 1;        // 0..31
            float wa = fsigmoid(w[kk * 32 + jj]);           // W_MAX = 1
            float pa = PI2F * fsigmoid(phi[kk * 32 + jj]);  // PHI_MAX = 2*pi
            float sp, cp;
            __sincosf(pa, &sp, &cp);
            A  = wa * cp;
            Bv = wa * sp;
        }
        sAB[(m & 31) * 32 + (m >> 5)] = make_float2(A, Bv);  // store [j][i]
    }

    // per-lane activations (2*pi*V_MAX*sig(v), B_MAX*sig(b), C_MAX*sig(c))
    const float tpv = (PI2F * 5.0f) * fsigmoid(v[lane]);
    const float ba  = 2.0f  * fsigmoid(b[lane]);
    const float ca  = 10.0f * fsigmoid(c[lane]);

    __syncthreads();

    const int rowBase = gw * 8;         // 8 rows per warp, two 4-row quads

    #pragma unroll
    for (int q = 0; q < 2; q++) {
        const int r0 = rowBase + q * 4;
        float sv[4], cv[4], xv[4], yv[4];

        #pragma unroll
        for (int t = 0; t < 4; t++) {
            const int row = r0 + t;
            float psi = 0.0f, rr = 0.0f, rd = 0.0f;
            if (row < nrows) {
                const float* rp = in + (size_t)row * 96;
                psi = rp[lane];
                rr  = rp[32 + lane];
                rd  = rp[64 + lane];
            }
            __sincosf(psi, &sv[t], &cv[t]);
            xv[t] = rr * sv[t];
            yv[t] = rr * cv[t];
            if (row < nrows) {
                float rdd = ca * (0.25f * ca * (ba - rr) - rd);
                float* op = out + (size_t)row * 96;
                op[32 + lane] = rd;
                op[64 + lane] = rdd;
            }
        }

        __syncwarp();   // quad 0 readers done before overwrite
        sXY[wib][0][lane] = make_float4(xv[0], xv[1], yv[0], yv[1]);
        sXY[wib][1][lane] = make_float4(xv[2], xv[3], yv[2], yv[3]);
        __syncwarp();

        // accumulators: P1=sum(Ax), P2=sum(By), Q1=sum(Ay), Q2=sum(Bx)
        u64 aP1 = 0, aP2 = 0, aQ1 = 0, aQ2 = 0;   // rows (0,1)
        u64 bP1 = 0, bP2 = 0, bQ1 = 0, bQ2 = 0;   // rows (2,3)

        #pragma unroll
        for (int j = 0; j < 32; j++) {
            float2 ab = sAB[j * 32 + lane];        // LDS.64, conflict-free
            u64 AA = pack2(ab.x, ab.x);            // {A,A}
            u64 BB = pack2(ab.y, ab.y);            // {B,B}
            float4 v0 = sXY[wib][0][j];            // broadcast LDS.128
            float4 v1 = sXY[wib][1][j];
            u64 X0 = pack2(v0.x, v0.y), Y0 = pack2(v0.z, v0.w);
            u64 X1 = pack2(v1.x, v1.y), Y1 = pack2(v1.z, v1.w);
            FMA2(aP1, AA, X0);  FMA2(aP2, BB, Y0);
            FMA2(aQ1, AA, Y0);  FMA2(aQ2, BB, X0);
            FMA2(bP1, AA, X1);  FMA2(bP2, BB, Y1);
            FMA2(bQ1, AA, Y1);  FMA2(bQ2, BB, X1);
        }

        float P[4], Q[4];
        {
            float l0,h0,l1,h1,l2,h2,l3,h3;
            unpack2(aP1,l0,h0); unpack2(aP2,l1,h1);
            unpack2(aQ1,l2,h2); unpack2(aQ2,l3,h3);
            P[0] = l0 - l1;  P[1] = h0 - h1;
            Q[0] = l2 + l3;  Q[1] = h2 + h3;
        }
        {
            float l0,h0,l1,h1,l2,h2,l3,h3;
            unpack2(bP1,l0,h0); unpack2(bP2,l1,h1);
            unpack2(bQ1,l2,h2); unpack2(bQ2,l3,h3);
            P[2] = l0 - l1;  P[3] = h0 - h1;
            Q[2] = l2 + l3;  Q[3] = h2 + h3;
        }

        #pragma unroll
        for (int t = 0; t < 4; t++) {
            const int row = r0 + t;
            if (row < nrows) {
                float psi_dot = tpv + cv[t] * P[t] - sv[t] * Q[t];
                out[(size_t)row * 96 + lane] = psi_dot;
            }
        }
    }
}

extern "C" void kernel_launch(void* const* d_in, const int* in_sizes, int n_in,
                              void* d_out, int out_size) {
    const float* states = (const float*)d_in[0];
    const float* v      = (const float*)d_in[1];
    const float* b      = (const float*)d_in[2];
    const float* c      = (const float*)d_in[3];
    const float* w      = (const float*)d_in[4];
    const float* phi    = (const float*)d_in[5];
    float* out = (float*)d_out;

    const int nrows = in_sizes[0] / 96;     // 65536
    const int rows_per_warp = 8;
    const int warps  = (nrows + rows_per_warp - 1) / rows_per_warp;
    const int blocks = (warps + 7) / 8;     // 8 warps (256 threads) per block

    hopf_kernel<<<blocks, 256>>>(states, out, v, b, c, w, phi, nrows);
}